// round 4
// baseline (speedup 1.0000x reference)
#include <cuda_runtime.h>
#include <cstddef>

// Problem constants
#define LSEQ   4096
#define LH     2048     // half domain after radix-2 split
#define LMASK  4095
#define MODES  64
#define NF2    128      // 2*MODES (real/imag interleaved)
#define NE     64
#define NO     64
#define NH     8
#define NBH    128
#define XCH    (NBH * NE * NF2)   // one DFT partial-chunk buffer (1M floats)

// Scratch (static device arrays: allocation-free)
__device__ float g_F[LH * NF2];          // fwd basis  [l<2048][2f]=cos,[2f+1]=-sin (1MB)
__device__ float g_G[NF2 * LH];          // inv basis  [2f][l<2048]=cos,[2f+1]=sin  (1MB)
__device__ float g_X[4 * XCH];           // DFT partials [chunk][bh][e][2f]         (16MB)
__device__ float g_C[NBH * NO * NF2];    // folded coeffs [bh][o][k]                (4MB)

// ---------------------------------------------------------------------------
// Basis init (half-domain only): double sincospi for accuracy.
// ---------------------------------------------------------------------------
__global__ void init_basis_kernel() {
    int idx = blockIdx.x * blockDim.x + threadIdx.x;   // < LH*MODES
    int l = idx >> 6;          // 0..2047
    int f = idx & 63;
    int k = (l * f) & LMASK;
    double s, c;
    sincospi((double)k / 2048.0, &s, &c);              // 2*pi*k/4096
    float cf = (float)c, sf = (float)s;
    g_F[l * NF2 + 2 * f]     = cf;
    g_F[l * NF2 + 2 * f + 1] = -sf;
    g_G[(2 * f) * LH + l]     = cf;
    g_G[(2 * f + 1) * LH + l] = sf;
}

// ---------------------------------------------------------------------------
// Stage 1: radix-2 truncated DFT. Block = (chunk of 512 half-domain l, bh).
// u = q[l] + q[l+2048] feeds even-f columns; v = q[l]-q[l+2048] feeds odd-f.
// Register-staged prefetch: LDG next tile during compute of current tile.
// ---------------------------------------------------------------------------
__global__ __launch_bounds__(256) void dft_kernel(const float* __restrict__ q) {
    __shared__ float u_s[32][64];    // 8KB
    __shared__ float v_s[32][64];    // 8KB
    __shared__ float F_s[32][128];   // 16KB
    const int bh = blockIdx.x & 127;
    const int chunk = blockIdx.x >> 7;           // 0..3
    const int b = bh >> 3, h = bh & 7;
    const int t = threadIdx.x;
    const int fb = (t & 31) * 4;     // cols 4c..4c+3 = f=2c (even) then f=2c+1 (odd)
    const int eb = (t >> 5) * 8;
    const float* qbase = q + ((size_t)b * LSEQ) * 512 + (size_t)h * 64;
    const int l_begin = chunk * 512;

    // loader indices
    const int ql_l  = t >> 4;            // 0..15 base (2 rows apart)
    const int ql_e4 = (t & 15) * 4;
    const int fl_l  = t >> 5;            // 0..7 base (8 rows apart)
    const int fl_f4 = (t & 31) * 4;

    float4 ra[2], rb[2], rf[4];
    auto LDG_TILE = [&](int l0) {
        #pragma unroll
        for (int r = 0; r < 2; ++r) {
            const float* p = qbase + (size_t)(l0 + ql_l + r * 16) * 512 + ql_e4;
            ra[r] = *(const float4*)p;
            rb[r] = *(const float4*)(p + (size_t)LH * 512);
        }
        #pragma unroll
        for (int r = 0; r < 4; ++r)
            rf[r] = *(const float4*)(g_F + (size_t)(l0 + fl_l + r * 8) * NF2 + fl_f4);
    };

    float acc[8][4];
    #pragma unroll
    for (int i = 0; i < 8; ++i)
        #pragma unroll
        for (int j = 0; j < 4; ++j) acc[i][j] = 0.f;

    LDG_TILE(l_begin);
    for (int tile = 0; tile < 16; ++tile) {
        const int l0 = l_begin + tile * 32;
        __syncthreads();   // previous compute done
        #pragma unroll
        for (int r = 0; r < 2; ++r) {
            int l = ql_l + r * 16;
            *(float4*)&u_s[l][ql_e4] = make_float4(ra[r].x + rb[r].x, ra[r].y + rb[r].y,
                                                   ra[r].z + rb[r].z, ra[r].w + rb[r].w);
            *(float4*)&v_s[l][ql_e4] = make_float4(ra[r].x - rb[r].x, ra[r].y - rb[r].y,
                                                   ra[r].z - rb[r].z, ra[r].w - rb[r].w);
        }
        #pragma unroll
        for (int r = 0; r < 4; ++r)
            *(float4*)&F_s[fl_l + r * 8][fl_f4] = rf[r];
        __syncthreads();
        if (tile < 15) LDG_TILE(l0 + 32);

        #pragma unroll 8
        for (int l = 0; l < 32; ++l) {
            float4 fv = *(float4*)&F_s[l][fb];
            float4 ua = *(float4*)&u_s[l][eb];
            float4 ub = *(float4*)&u_s[l][eb + 4];
            float4 va = *(float4*)&v_s[l][eb];
            float4 vb = *(float4*)&v_s[l][eb + 4];
            float ur[8] = {ua.x, ua.y, ua.z, ua.w, ub.x, ub.y, ub.z, ub.w};
            float vr[8] = {va.x, va.y, va.z, va.w, vb.x, vb.y, vb.z, vb.w};
            #pragma unroll
            for (int i = 0; i < 8; ++i) {
                acc[i][0] += ur[i] * fv.x;
                acc[i][1] += ur[i] * fv.y;
                acc[i][2] += vr[i] * fv.z;
                acc[i][3] += vr[i] * fv.w;
            }
        }
    }
    float* xb = g_X + (size_t)chunk * XCH + ((size_t)bh * NE + eb) * NF2 + fb;
    #pragma unroll
    for (int i = 0; i < 8; ++i)
        *(float4*)(xb + (size_t)i * NF2) =
            make_float4(acc[i][0], acc[i][1], acc[i][2], acc[i][3]);
}

// ---------------------------------------------------------------------------
// Stage 2: complex mode mix + irfft coefficient folding. One block per (b,h).
// ---------------------------------------------------------------------------
__global__ __launch_bounds__(256) void mix_kernel(const float* __restrict__ wr,
                                                  const float* __restrict__ wi) {
    __shared__ float X_s[NE][NF2];   // 32KB
    const int bh = blockIdx.x;
    const int h = bh & 7;
    const int t = threadIdx.x;
    for (int idx = t; idx < NE * NF2; idx += 256) {
        float s = 0.f;
        #pragma unroll
        for (int c = 0; c < 4; ++c)
            s += g_X[(size_t)c * XCH + (size_t)bh * NE * NF2 + idx];
        ((float*)X_s)[idx] = s;
    }
    __syncthreads();

    const int f2 = t & 31;
    const int og = t >> 5;
    const float a0 = (f2 == 0) ? (1.0f / 4096.0f) : (2.0f / 4096.0f);
    const float a1 = 2.0f / 4096.0f;

    #pragma unroll
    for (int oi = 0; oi < 8; ++oi) {
        int o = og * 8 + oi;
        const float* wrp = wr + ((size_t)(h * 64) * 64 + o) * 64 + 2 * f2;
        const float* wip = wi + ((size_t)(h * 64) * 64 + o) * 64 + 2 * f2;
        float ar0 = 0.f, ai0 = 0.f, ar1 = 0.f, ai1 = 0.f;
        #pragma unroll 4
        for (int e = 0; e < 64; ++e) {
            float4 x = *(float4*)&X_s[e][4 * f2];
            float2 wre = *(const float2*)(wrp + (size_t)e * 4096);
            float2 wie = *(const float2*)(wip + (size_t)e * 4096);
            ar0 += x.x * wre.x - x.y * wie.x;
            ai0 += x.x * wie.x + x.y * wre.x;
            ar1 += x.z * wre.y - x.w * wie.y;
            ai1 += x.z * wie.y + x.w * wre.y;
        }
        *(float4*)(g_C + ((size_t)bh * NO + o) * NF2 + 4 * f2) =
            make_float4(a0 * ar0, -a0 * ai0, a1 * ar1, -a1 * ai1);
    }
}

// ---------------------------------------------------------------------------
// Stage 3: inverse transform, even/odd folded. Block = (bh, 128 half-domain l).
// accE sums even-f terms, accO odd-f; out(l)=E+O, out(l+2048)=E-O.
// C transposed in smem (pad 68: 16B-aligned rows); G prefetched via regs.
// ---------------------------------------------------------------------------
#define CTP 68
__global__ __launch_bounds__(256) void idft_kernel(float* __restrict__ out) {
    __shared__ float Ct[NF2][CTP];   // 34.8KB
    __shared__ float G_s[16][128];   // 8KB
    const int bh = blockIdx.x & 127;
    const int lb = blockIdx.x >> 7;        // 0..15
    const int t = threadIdx.x;
    const int lbase = lb * 128;            // half-domain l base
    const int lane = t & 31;
    const int c0 = lane * 4;
    const int ob = (t >> 5) * 8;

    // transposed C fill (one-time)
    #pragma unroll
    for (int r = 0; r < 32; ++r) {
        int idx = t + r * 256;
        int o = idx >> 7, k = idx & 127;
        Ct[k][o] = g_C[(size_t)bh * NO * NF2 + idx];
    }

    // G prefetch indices: 2 float4 per thread per 16-k tile
    const int gl_k  = t >> 5;              // 0..7 base (8 rows apart)
    const int gl_l4 = (t & 31) * 4;
    float4 rg[2];
    auto LDG_G = [&](int kc) {
        #pragma unroll
        for (int r = 0; r < 2; ++r)
            rg[r] = *(const float4*)(g_G + (size_t)(kc + gl_k + r * 8) * LH + lbase + gl_l4);
    };

    float accE[8][4], accO[8][4];
    #pragma unroll
    for (int i = 0; i < 8; ++i)
        #pragma unroll
        for (int j = 0; j < 4; ++j) { accE[i][j] = 0.f; accO[i][j] = 0.f; }

    LDG_G(0);
    for (int kc = 0; kc < 128; kc += 16) {
        __syncthreads();
        #pragma unroll
        for (int r = 0; r < 2; ++r)
            *(float4*)&G_s[gl_k + r * 8][gl_l4] = rg[r];
        __syncthreads();
        if (kc < 112) LDG_G(kc + 16);

        #pragma unroll
        for (int kk = 0; kk < 16; ++kk) {
            float4 g = *(float4*)&G_s[kk][c0];
            float4 cva = *(float4*)&Ct[kc + kk][ob];       // broadcast
            float4 cvb = *(float4*)&Ct[kc + kk][ob + 4];   // broadcast
            float cv[8] = {cva.x, cva.y, cva.z, cva.w, cvb.x, cvb.y, cvb.z, cvb.w};
            if (((kk >> 1) & 1) == 0) {
                #pragma unroll
                for (int i = 0; i < 8; ++i) {
                    accE[i][0] += cv[i] * g.x;
                    accE[i][1] += cv[i] * g.y;
                    accE[i][2] += cv[i] * g.z;
                    accE[i][3] += cv[i] * g.w;
                }
            } else {
                #pragma unroll
                for (int i = 0; i < 8; ++i) {
                    accO[i][0] += cv[i] * g.x;
                    accO[i][1] += cv[i] * g.y;
                    accO[i][2] += cv[i] * g.z;
                    accO[i][3] += cv[i] * g.w;
                }
            }
        }
    }

    #pragma unroll
    for (int i = 0; i < 8; ++i) {
        float* op = out + ((size_t)bh * NO + ob + i) * LSEQ + lbase + c0;
        *(float4*)op = make_float4(accE[i][0] + accO[i][0], accE[i][1] + accO[i][1],
                                   accE[i][2] + accO[i][2], accE[i][3] + accO[i][3]);
        *(float4*)(op + LH) = make_float4(accE[i][0] - accO[i][0], accE[i][1] - accO[i][1],
                                          accE[i][2] - accO[i][2], accE[i][3] - accO[i][3]);
    }
}

// ---------------------------------------------------------------------------
extern "C" void kernel_launch(void* const* d_in, const int* in_sizes, int n_in,
                              void* d_out, int out_size) {
    const float* q = (const float*)d_in[0];
    const float* wr = nullptr;
    const float* wi = nullptr;
    for (int i = 0; i < n_in; ++i) {
        if (in_sizes[i] == NH * NE * NO * MODES) {
            if (!wr) wr = (const float*)d_in[i];
            else if (!wi) wi = (const float*)d_in[i];
        }
    }
    float* out = (float*)d_out;

    init_basis_kernel<<<(LH * MODES) / 256, 256>>>();
    dft_kernel<<<512, 256>>>(q);
    mix_kernel<<<NBH, 256>>>(wr, wi);
    idft_kernel<<<NBH * 16, 256>>>(out);
}

// round 6
// speedup vs baseline: 1.7993x; 1.7993x over previous
#include <cuda_runtime.h>
#include <cuda_bf16.h>
#include <cstdint>
#include <cstddef>

#define LSEQ 4096
#define NF2  128
#define NBH  128

// ------------------------------------------------------------- gmem scratch
__device__ __nv_bfloat16 g_Fhi[NF2 * LSEQ];            // fwd basis [f2][l]
__device__ __nv_bfloat16 g_Flo[NF2 * LSEQ];
__device__ __nv_bfloat16 g_Gthi[LSEQ * NF2];           // inv basis [l][k]
__device__ __nv_bfloat16 g_Gtlo[LSEQ * NF2];
__device__ __nv_bfloat16 g_qThi[(size_t)NBH * 64 * LSEQ];  // [bh*64+e][l]
__device__ __nv_bfloat16 g_qTlo[(size_t)NBH * 64 * LSEQ];
__device__ float         g_X[NBH * 64 * NF2];          // [bh][e][f2]
__device__ __nv_bfloat16 g_Chi[NBH * 64 * NF2];        // [bh*64+o][k]
__device__ __nv_bfloat16 g_Clo[NBH * 64 * NF2];

// ------------------------------------------------------------- helpers
__device__ __forceinline__ uint32_t smem_u32(const void* p) {
    uint32_t a;
    asm("{ .reg .u64 t; cvta.to.shared.u64 t, %1; cvt.u32.u64 %0, t; }" : "=r"(a) : "l"(p));
    return a;
}
__device__ __forceinline__ void split_bf16(float x, __nv_bfloat16& hi, __nv_bfloat16& lo) {
    hi = __float2bfloat16(x);
    lo = __float2bfloat16(x - __bfloat162float(hi));
}
__device__ __forceinline__ void ldsm4(uint32_t* r, uint32_t addr) {
    asm volatile("ldmatrix.sync.aligned.m8n8.x4.shared.b16 {%0,%1,%2,%3}, [%4];"
                 : "=r"(r[0]), "=r"(r[1]), "=r"(r[2]), "=r"(r[3]) : "r"(addr));
}
__device__ __forceinline__ void mma16816(float* d, const uint32_t* a, const uint32_t* b) {
    asm volatile("mma.sync.aligned.m16n8k16.row.col.f32.bf16.bf16.f32 "
                 "{%0,%1,%2,%3}, {%4,%5,%6,%7}, {%8,%9}, {%0,%1,%2,%3};"
                 : "+f"(d[0]), "+f"(d[1]), "+f"(d[2]), "+f"(d[3])
                 : "r"(a[0]), "r"(a[1]), "r"(a[2]), "r"(a[3]), "r"(b[0]), "r"(b[1]));
}
#define CP16(sa, gp) asm volatile("cp.async.cg.shared.global [%0], [%1], 16;" \
                                  :: "r"((uint32_t)(sa)), "l"(gp) : "memory")
#define CP_COMMIT()  asm volatile("cp.async.commit_group;" ::: "memory")
#define CP_WAIT0()   asm volatile("cp.async.wait_group 0;" ::: "memory")
#define CP_WAIT1()   asm volatile("cp.async.wait_group 1;" ::: "memory")

// ---------------------------------------------------------------- basis init
__global__ void init_basis_kernel() {
    int idx = blockIdx.x * 256 + threadIdx.x;     // < 262144
    {   // F rows: [2f]=cos, [2f+1]=-sin; l-fast
        int f = idx >> 12, l = idx & 4095;
        float s, c;
        sincospif((float)((l * f) & 4095) / 2048.0f, &s, &c);
        __nv_bfloat16 hi, lo;
        split_bf16(c, hi, lo);
        g_Fhi[(2 * f) * LSEQ + l] = hi;  g_Flo[(2 * f) * LSEQ + l] = lo;
        split_bf16(-s, hi, lo);
        g_Fhi[(2 * f + 1) * LSEQ + l] = hi;  g_Flo[(2 * f + 1) * LSEQ + l] = lo;
    }
    {   // Gt rows [l]: k=2f cos, k=2f+1 sin; k-fast
        int l = idx >> 6, f = idx & 63;
        float s, c;
        sincospif((float)((l * f) & 4095) / 2048.0f, &s, &c);
        __nv_bfloat16 hi, lo;
        split_bf16(c, hi, lo);
        g_Gthi[l * NF2 + 2 * f] = hi;  g_Gtlo[l * NF2 + 2 * f] = lo;
        split_bf16(s, hi, lo);
        g_Gthi[l * NF2 + 2 * f + 1] = hi;  g_Gtlo[l * NF2 + 2 * f + 1] = lo;
    }
}

// ------------------------------------------------ transpose+split: q -> qT bf16
__global__ __launch_bounds__(256) void transpose_split_kernel(const float* __restrict__ q) {
    __shared__ float ts[64][65];
    const int bh = blockIdx.x >> 6, lc = blockIdx.x & 63;
    const int b = bh >> 3, h = bh & 7, t = threadIdx.x;
    const float* qb = q + (((size_t)b * LSEQ + lc * 64) * 8 + h) * 64;
    #pragma unroll
    for (int i = 0; i < 4; ++i) {
        int c = t + i * 256;
        int l = c >> 4, e4 = (c & 15) * 4;
        float4 v = *(const float4*)(qb + (size_t)l * 512 + e4);
        ts[l][e4] = v.x; ts[l][e4 + 1] = v.y; ts[l][e4 + 2] = v.z; ts[l][e4 + 3] = v.w;
    }
    __syncthreads();
    #pragma unroll
    for (int i = 0; i < 2; ++i) {
        int c = t + i * 256;
        int e = c >> 3, lg = (c & 7) * 8;
        union { uint4 v; __nv_bfloat16 x[8]; } uh, ul;
        #pragma unroll
        for (int j = 0; j < 8; ++j) {
            float f = ts[lg + j][e];
            __nv_bfloat16 hi, lo;
            split_bf16(f, hi, lo);
            uh.x[j] = hi;  ul.x[j] = lo;
        }
        size_t off = ((size_t)bh * 64 + e) * LSEQ + lc * 64 + lg;
        *(uint4*)&g_qThi[off] = uh.v;
        *(uint4*)&g_qTlo[off] = ul.v;
    }
}

// ---------------------------------------------------------------- Stage 1: DFT
// CTA/bh: D[128 f2, 64 e] = F[128,4096] x qT[64,4096]^T via HMMA, K-chunks of 64,
// cp.async double-buffered, 3 hi/lo passes. smem rows padded +16B (conflict-free LDSM).
#define D_AS   18432                 // A array: 128 rows * 144B
#define D_BS   9216                  // B array: 64 rows * 144B
#define D_STG  (2 * D_AS + 2 * D_BS) // 55296
#define DFT_SMEM (2 * D_STG)

__global__ __launch_bounds__(256) void dft_mma_kernel() {
    extern __shared__ char smd[];
    const uint32_t sb = smem_u32(smd);
    const int bh = blockIdx.x, t = threadIdx.x;
    const int w = t >> 5, lane = t & 31;
    const size_t qtb = (size_t)bh * 64 * LSEQ;

    // ldmatrix lane offsets (bytes, within array; row stride 144)
    const uint32_t aoff = (uint32_t)(w * 16 + (lane & 15)) * 144 + (lane >> 4) * 16;
    const uint32_t boff = (uint32_t)((lane >> 4) * 8 + (lane & 7)) * 144 + ((lane >> 3) & 1) * 16;

    float acc[8][4];
    #pragma unroll
    for (int i = 0; i < 8; ++i)
        #pragma unroll
        for (int j = 0; j < 4; ++j) acc[i][j] = 0.f;

    auto issue = [&](int c, uint32_t stg) {
        const size_t k0 = (size_t)c * 64;
        #pragma unroll
        for (int i = 0; i < 4; ++i) {                    // A: F chunk [128][64] hi/lo
            int cc = t + i * 256;
            int row = cc >> 3, kg = (cc & 7) * 8;
            uint32_t so = (uint32_t)row * 144 + kg * 2;
            CP16(stg + so,        g_Fhi + (size_t)row * LSEQ + k0 + kg);
            CP16(stg + D_AS + so, g_Flo + (size_t)row * LSEQ + k0 + kg);
        }
        #pragma unroll
        for (int i = 0; i < 2; ++i) {                    // B: qT chunk [64][64] hi/lo
            int cc = t + i * 256;
            int e = cc >> 3, kg = (cc & 7) * 8;
            uint32_t so = (uint32_t)e * 144 + kg * 2;
            CP16(stg + 2 * D_AS + so,        g_qThi + qtb + (size_t)e * LSEQ + k0 + kg);
            CP16(stg + 2 * D_AS + D_BS + so, g_qTlo + qtb + (size_t)e * LSEQ + k0 + kg);
        }
        CP_COMMIT();
    };

    issue(0, sb);
    for (int c = 0; c < 64; ++c) {
        if (c < 63) { issue(c + 1, sb + ((c + 1) & 1) * D_STG); CP_WAIT1(); }
        else        { CP_WAIT0(); }
        __syncthreads();
        const uint32_t stg = sb + (c & 1) * D_STG;
        const uint32_t aHi = stg + aoff, aLo = stg + D_AS + aoff;
        const uint32_t bHi = stg + 2 * D_AS + boff, bLo = stg + 2 * D_AS + D_BS + boff;
        #pragma unroll
        for (int ks = 0; ks < 4; ++ks) {
            uint32_t ah[4], al[4];
            ldsm4(ah, aHi + ks * 32);
            ldsm4(al, aLo + ks * 32);
            #pragma unroll
            for (int j = 0; j < 4; ++j) {
                uint32_t bh_[4], bl_[4];
                ldsm4(bh_, bHi + j * 2304 + ks * 32);    // 2304 = 16*144
                ldsm4(bl_, bLo + j * 2304 + ks * 32);
                mma16816(acc[2 * j],     ah, bh_);
                mma16816(acc[2 * j],     ah, bl_);
                mma16816(acc[2 * j],     al, bh_);
                mma16816(acc[2 * j + 1], ah, bh_ + 2);
                mma16816(acc[2 * j + 1], ah, bl_ + 2);
                mma16816(acc[2 * j + 1], al, bh_ + 2);
            }
        }
        __syncthreads();
    }

    // epilogue: D[f2=row][e=col] -> g_X[bh][e][f2]
    const int g = lane >> 2, q4 = lane & 3;
    float* xb = g_X + (size_t)bh * 8192;
    const int r0 = w * 16 + g, r1 = r0 + 8;
    #pragma unroll
    for (int j = 0; j < 8; ++j) {
        int e0 = j * 8 + q4 * 2;
        xb[e0 * 128 + r0]       = acc[j][0];
        xb[(e0 + 1) * 128 + r0] = acc[j][1];
        xb[e0 * 128 + r1]       = acc[j][2];
        xb[(e0 + 1) * 128 + r1] = acc[j][3];
    }
}

// ---------------------------------------------------------------- Stage 2: mix
#define MIX_SMEM 131072      // Ws_r 32K | Ws_i 32K | Xs 64K
__global__ __launch_bounds__(256) void mix_kernel(const float* __restrict__ wr,
                                                  const float* __restrict__ wi) {
    extern __shared__ char sm[];
    float* Ws_r = (float*)sm;                // [16e][8o][64m]
    float* Ws_i = (float*)(sm + 32768);
    float* Xs   = (float*)(sm + 65536);      // [8b][16e][128]
    const int h = blockIdx.x & 7, og = (blockIdx.x >> 3) & 7, bhalf = blockIdx.x >> 6;
    const int t = threadIdx.x;
    const int f2 = t & 31, ol = t >> 5;

    float acc[8][4];
    #pragma unroll
    for (int i = 0; i < 8; ++i)
        #pragma unroll
        for (int j = 0; j < 4; ++j) acc[i][j] = 0.f;

    for (int e0 = 0; e0 < 64; e0 += 16) {
        __syncthreads();
        #pragma unroll
        for (int i = 0; i < 8; ++i) {
            int c = t + i * 256;
            int row = c >> 4, m4 = (c & 15) * 4;
            int e = row >> 3, o = row & 7;
            size_t g = (((size_t)h * 64 + e0 + e) * 64 + og * 8 + o) * 64 + m4;
            *(float4*)&Ws_r[(e * 8 + o) * 64 + m4] = *(const float4*)&wr[g];
            *(float4*)&Ws_i[(e * 8 + o) * 64 + m4] = *(const float4*)&wi[g];
        }
        #pragma unroll
        for (int i = 0; i < 16; ++i) {
            int c = t + i * 256;
            int row = c >> 5, f4 = (c & 31) * 4;
            int b = row >> 4, e = row & 15;
            int bh = (bhalf * 8 + b) * 8 + h;
            *(float4*)&Xs[(b * 16 + e) * 128 + f4] =
                *(const float4*)&g_X[(size_t)bh * 8192 + (e0 + e) * 128 + f4];
        }
        __syncthreads();
        #pragma unroll 4
        for (int e = 0; e < 16; ++e) {
            float2 w_r = *(float2*)&Ws_r[(e * 8 + ol) * 64 + 2 * f2];
            float2 w_i = *(float2*)&Ws_i[(e * 8 + ol) * 64 + 2 * f2];
            #pragma unroll
            for (int b = 0; b < 8; ++b) {
                float4 x = *(float4*)&Xs[(b * 16 + e) * 128 + 4 * f2];
                acc[b][0] += x.x * w_r.x - x.y * w_i.x;
                acc[b][1] += x.x * w_i.x + x.y * w_r.x;
                acc[b][2] += x.z * w_r.y - x.w * w_i.y;
                acc[b][3] += x.z * w_i.y + x.w * w_r.y;
            }
        }
    }
    const float a0 = (f2 == 0) ? (1.0f / 4096.0f) : (2.0f / 4096.0f);
    const float a1 = 2.0f / 4096.0f;
    #pragma unroll
    for (int b = 0; b < 8; ++b) {
        size_t row = (size_t)((bhalf * 8 + b) * 8 + h) * 64 + og * 8 + ol;
        float v[4] = {a0 * acc[b][0], -a0 * acc[b][1], a1 * acc[b][2], -a1 * acc[b][3]};
        union { uint2 u; __nv_bfloat16 x[4]; } uh, ul;
        #pragma unroll
        for (int j = 0; j < 4; ++j) {
            __nv_bfloat16 hi, lo;
            split_bf16(v[j], hi, lo);
            uh.x[j] = hi;  ul.x[j] = lo;
        }
        *(uint2*)&g_Chi[row * NF2 + 4 * f2] = uh.u;
        *(uint2*)&g_Clo[row * NF2 + 4 * f2] = ul.u;
    }
}

// ---------------------------------------------------------------- Stage 3: iDFT
// CTA = (bh-pair p, 128-l chunk lc): D[128 rows, 128 l] = C2[128,128] x Gt[128-chunk,128]^T.
#define I_AS   34816                 // 128 rows * 272B
#define IDFT_SMEM (4 * I_AS)         // Ahi | Alo | Bhi | Blo = 139264

__global__ __launch_bounds__(256) void idft_mma_kernel(float* __restrict__ out) {
    extern __shared__ char smi[];
    const uint32_t sb = smem_u32(smi);
    const int p = blockIdx.x & 63, lc = blockIdx.x >> 6;     // p: bh-pair, lc: 0..31
    const int t = threadIdx.x;
    const int w = t >> 5, lane = t & 31;

    #pragma unroll
    for (int i = 0; i < 8; ++i) {                // A = C2 [128][128] hi/lo
        int cc = t + i * 256;
        int row = cc >> 4, kg = (cc & 15) * 8;
        uint32_t so = (uint32_t)row * 272 + kg * 2;
        size_t gsrc = ((size_t)p * 128 + row) * 128 + kg;
        CP16(sb + so,        g_Chi + gsrc);
        CP16(sb + I_AS + so, g_Clo + gsrc);
    }
    #pragma unroll
    for (int i = 0; i < 8; ++i) {                // B = Gt chunk [128 l][128 k] hi/lo
        int cc = t + i * 256;
        int row = cc >> 4, kg = (cc & 15) * 8;
        uint32_t so = (uint32_t)row * 272 + kg * 2;
        size_t gsrc = ((size_t)lc * 128 + row) * 128 + kg;
        CP16(sb + 2 * I_AS + so, g_Gthi + gsrc);
        CP16(sb + 3 * I_AS + so, g_Gtlo + gsrc);
    }
    CP_COMMIT();
    CP_WAIT0();
    __syncthreads();

    const uint32_t aoff = (uint32_t)(w * 16 + (lane & 15)) * 272 + (lane >> 4) * 16;
    const uint32_t boff = (uint32_t)((lane >> 4) * 8 + (lane & 7)) * 272 + ((lane >> 3) & 1) * 16;
    const uint32_t aHi = sb + aoff, aLo = sb + I_AS + aoff;
    const uint32_t bHi = sb + 2 * I_AS + boff, bLo = sb + 3 * I_AS + boff;

    float acc[16][4];
    #pragma unroll
    for (int i = 0; i < 16; ++i)
        #pragma unroll
        for (int j = 0; j < 4; ++j) acc[i][j] = 0.f;

    #pragma unroll
    for (int ks = 0; ks < 8; ++ks) {
        uint32_t ah[4], al[4];
        ldsm4(ah, aHi + ks * 32);
        ldsm4(al, aLo + ks * 32);
        #pragma unroll
        for (int j = 0; j < 8; ++j) {
            uint32_t bh_[4], bl_[4];
            ldsm4(bh_, bHi + j * 4352 + ks * 32);        // 4352 = 16*272
            ldsm4(bl_, bLo + j * 4352 + ks * 32);
            mma16816(acc[2 * j],     ah, bh_);
            mma16816(acc[2 * j],     ah, bl_);
            mma16816(acc[2 * j],     al, bh_);
            mma16816(acc[2 * j + 1], ah, bh_ + 2);
            mma16816(acc[2 * j + 1], ah, bl_ + 2);
            mma16816(acc[2 * j + 1], al, bh_ + 2);
        }
    }

    // epilogue: rows p*128+w*16+{g,g+8}, cols lc*128 + j*8 + q4*2
    const int g = lane >> 2, q4 = lane & 3;
    float* o0 = out + ((size_t)p * 128 + w * 16 + g) * LSEQ + lc * 128 + q4 * 2;
    float* o1 = o0 + (size_t)8 * LSEQ;
    #pragma unroll
    for (int j = 0; j < 16; ++j) {
        *(float2*)(o0 + j * 8) = make_float2(acc[j][0], acc[j][1]);
        *(float2*)(o1 + j * 8) = make_float2(acc[j][2], acc[j][3]);
    }
}

// ---------------------------------------------------------------------------
extern "C" void kernel_launch(void* const* d_in, const int* in_sizes, int n_in,
                              void* d_out, int out_size) {
    const float* q = (const float*)d_in[0];
    const float* wr = nullptr;
    const float* wi = nullptr;
    for (int i = 0; i < n_in; ++i) {
        if (in_sizes[i] == 8 * 64 * 64 * 64) {
            if (!wr) wr = (const float*)d_in[i];
            else if (!wi) wi = (const float*)d_in[i];
        }
    }
    float* out = (float*)d_out;

    cudaFuncSetAttribute(dft_mma_kernel,  cudaFuncAttributeMaxDynamicSharedMemorySize, DFT_SMEM);
    cudaFuncSetAttribute(mix_kernel,      cudaFuncAttributeMaxDynamicSharedMemorySize, MIX_SMEM);
    cudaFuncSetAttribute(idft_mma_kernel, cudaFuncAttributeMaxDynamicSharedMemorySize, IDFT_SMEM);

    init_basis_kernel<<<1024, 256>>>();
    transpose_split_kernel<<<NBH * 64, 256>>>(q);
    dft_mma_kernel<<<NBH, 256, DFT_SMEM>>>();
    mix_kernel<<<NBH, 256, MIX_SMEM>>>(wr, wi);
    idft_mma_kernel<<<64 * 32, 256, IDFT_SMEM>>>(out);
}

// round 7
// speedup vs baseline: 2.4993x; 1.3891x over previous
#include <cuda_runtime.h>
#include <cuda_bf16.h>
#include <cstdint>
#include <cstddef>

#define LSEQ 4096
#define LH   2048
#define NBH  128

// ------------------------------------------------------------- gmem scratch
// Forward basis, row-reordered: Fu rows ru=2*fe+c  <-> freq f=2*fe   (c=0 cos, c=1 -sin)
//                               Fv rows rv=2*fo+c  <-> freq f=2*fo+1
__device__ __nv_bfloat16 g_Fu_hi[64 * LH], g_Fu_lo[64 * LH];
__device__ __nv_bfloat16 g_Fv_hi[64 * LH], g_Fv_lo[64 * LH];
// Inverse basis split by freq parity: Gte[l][2*fe+c] (c=0 cos, c=1 sin), Gto likewise
__device__ __nv_bfloat16 g_Gte_hi[LH * 64], g_Gte_lo[LH * 64];
__device__ __nv_bfloat16 g_Gto_hi[LH * 64], g_Gto_lo[LH * 64];
// Butterflied input: u/v [bh*64+e][l<2048]
__device__ __nv_bfloat16 g_u_hi[(size_t)NBH * 64 * LH], g_u_lo[(size_t)NBH * 64 * LH];
__device__ __nv_bfloat16 g_v_hi[(size_t)NBH * 64 * LH], g_v_lo[(size_t)NBH * 64 * LH];
// Spectrum (natural f2 layout) and folded coeffs split by parity
__device__ float         g_X[NBH * 64 * 128];          // [bh][e][f2]
__device__ __nv_bfloat16 g_Ce_hi[NBH * 64 * 64], g_Ce_lo[NBH * 64 * 64];
__device__ __nv_bfloat16 g_Co_hi[NBH * 64 * 64], g_Co_lo[NBH * 64 * 64];

// ------------------------------------------------------------- helpers
__device__ __forceinline__ uint32_t smem_u32(const void* p) {
    uint32_t a;
    asm("{ .reg .u64 t; cvta.to.shared.u64 t, %1; cvt.u32.u64 %0, t; }" : "=r"(a) : "l"(p));
    return a;
}
__device__ __forceinline__ void split_bf16(float x, __nv_bfloat16& hi, __nv_bfloat16& lo) {
    hi = __float2bfloat16(x);
    lo = __float2bfloat16(x - __bfloat162float(hi));
}
__device__ __forceinline__ void ldsm4(uint32_t* r, uint32_t addr) {
    asm volatile("ldmatrix.sync.aligned.m8n8.x4.shared.b16 {%0,%1,%2,%3}, [%4];"
                 : "=r"(r[0]), "=r"(r[1]), "=r"(r[2]), "=r"(r[3]) : "r"(addr));
}
__device__ __forceinline__ void mma16816(float* d, const uint32_t* a, const uint32_t* b) {
    asm volatile("mma.sync.aligned.m16n8k16.row.col.f32.bf16.bf16.f32 "
                 "{%0,%1,%2,%3}, {%4,%5,%6,%7}, {%8,%9}, {%0,%1,%2,%3};"
                 : "+f"(d[0]), "+f"(d[1]), "+f"(d[2]), "+f"(d[3])
                 : "r"(a[0]), "r"(a[1]), "r"(a[2]), "r"(a[3]), "r"(b[0]), "r"(b[1]));
}
#define CP16(sa, gp) asm volatile("cp.async.cg.shared.global [%0], [%1], 16;" \
                                  :: "r"((uint32_t)(sa)), "l"(gp) : "memory")
#define CP_COMMIT()  asm volatile("cp.async.commit_group;" ::: "memory")
#define CP_WAIT0()   asm volatile("cp.async.wait_group 0;" ::: "memory")
#define CP_WAIT1()   asm volatile("cp.async.wait_group 1;" ::: "memory")

// ---------------------------------------------------------------- basis init
__global__ void init_basis_kernel() {
    int idx = blockIdx.x * 256 + threadIdx.x;      // < 131072
    {   // Fu/Fv: ru = 2*fe+c over half domain
        int ru = idx >> 11, l = idx & 2047;
        int fe = ru >> 1, c = ru & 1;
        float s, cs;
        __nv_bfloat16 hi, lo;
        int fu = 2 * fe;
        sincospif((float)((l * fu) & 4095) / 2048.0f, &s, &cs);
        split_bf16(c ? -s : cs, hi, lo);
        g_Fu_hi[ru * LH + l] = hi;  g_Fu_lo[ru * LH + l] = lo;
        int fv = 2 * fe + 1;
        sincospif((float)((l * fv) & 4095) / 2048.0f, &s, &cs);
        split_bf16(c ? -s : cs, hi, lo);
        g_Fv_hi[ru * LH + l] = hi;  g_Fv_lo[ru * LH + l] = lo;
    }
    {   // Gte/Gto: [l][kk=2*fe+c], c=0 cos, c=1 +sin
        int l = idx >> 6, kk = idx & 63;
        int fe = kk >> 1, c = kk & 1;
        float s, cs;
        __nv_bfloat16 hi, lo;
        int f_e = 2 * fe;
        sincospif((float)((l * f_e) & 4095) / 2048.0f, &s, &cs);
        split_bf16(c ? s : cs, hi, lo);
        g_Gte_hi[l * 64 + kk] = hi;  g_Gte_lo[l * 64 + kk] = lo;
        int f_o = 2 * fe + 1;
        sincospif((float)((l * f_o) & 4095) / 2048.0f, &s, &cs);
        split_bf16(c ? s : cs, hi, lo);
        g_Gto_hi[l * 64 + kk] = hi;  g_Gto_lo[l * 64 + kk] = lo;
    }
}

// ------------------------------------- transpose + butterfly + split: q -> u,v
__global__ __launch_bounds__(256) void transpose_bfly_kernel(const float* __restrict__ q) {
    __shared__ float tsA[64][65], tsB[64][65];
    const int bh = blockIdx.x >> 5, lc = blockIdx.x & 31;
    const int b = bh >> 3, h = bh & 7, t = threadIdx.x;
    const int l0 = lc * 64;
    const float* qbA = q + (((size_t)b * LSEQ + l0) * 8 + h) * 64;
    const float* qbB = qbA + (size_t)LH * 512;
    #pragma unroll
    for (int i = 0; i < 4; ++i) {
        int c = t + i * 256;
        int l = c >> 4, e4 = (c & 15) * 4;
        float4 va = *(const float4*)(qbA + (size_t)l * 512 + e4);
        float4 vb = *(const float4*)(qbB + (size_t)l * 512 + e4);
        tsA[l][e4] = va.x; tsA[l][e4+1] = va.y; tsA[l][e4+2] = va.z; tsA[l][e4+3] = va.w;
        tsB[l][e4] = vb.x; tsB[l][e4+1] = vb.y; tsB[l][e4+2] = vb.z; tsB[l][e4+3] = vb.w;
    }
    __syncthreads();
    #pragma unroll
    for (int i = 0; i < 2; ++i) {
        int c = t + i * 256;
        int e = c >> 3, lg = (c & 7) * 8;
        union { uint4 v; __nv_bfloat16 x[8]; } uh, ul, vh, vl;
        #pragma unroll
        for (int j = 0; j < 8; ++j) {
            float a = tsA[lg + j][e], bb = tsB[lg + j][e];
            __nv_bfloat16 hi, lo;
            split_bf16(a + bb, hi, lo); uh.x[j] = hi; ul.x[j] = lo;
            split_bf16(a - bb, hi, lo); vh.x[j] = hi; vl.x[j] = lo;
        }
        size_t off = ((size_t)bh * 64 + e) * LH + l0 + lg;
        *(uint4*)&g_u_hi[off] = uh.v;  *(uint4*)&g_u_lo[off] = ul.v;
        *(uint4*)&g_v_hi[off] = vh.v;  *(uint4*)&g_v_lo[off] = vl.v;
    }
}

// ---------------------------------------------------------------- Stage 1: DFT
// CTA/bh. Two GEMMs: Xu[64 ru,64 e]=Fu*u^T, Xv=Fv*v^T over K=2048 (chunks of 64).
// Warps 0-3 -> u-group, 4-7 -> v-group. 3 hi/lo passes. cp.async double-buffered.
#define D_ARR  9216                  // 64 rows * 144B
#define D_STG  (8 * D_ARR)           // 73728
#define DFT_SMEM (2 * D_STG)         // 147456

__global__ __launch_bounds__(256) void dft_mma_kernel() {
    extern __shared__ char smd[];
    const uint32_t sb = smem_u32(smd);
    const int bh = blockIdx.x, t = threadIdx.x;
    const int w = t >> 5, lane = t & 31;
    const int grp = w >> 2, wr = w & 3;
    const size_t qtb = (size_t)bh * 64 * LH;

    const __nv_bfloat16* srcs[8] = {
        g_Fu_hi, g_Fu_lo, g_Fv_hi, g_Fv_lo,
        g_u_hi + qtb, g_u_lo + qtb, g_v_hi + qtb, g_v_lo + qtb };

    const uint32_t aoff = (uint32_t)(wr * 16 + (lane & 15)) * 144 + (lane >> 4) * 16;
    const uint32_t boff = (uint32_t)((lane >> 4) * 8 + (lane & 7)) * 144 + ((lane >> 3) & 1) * 16;

    float acc[8][4];
    #pragma unroll
    for (int i = 0; i < 8; ++i)
        #pragma unroll
        for (int j = 0; j < 4; ++j) acc[i][j] = 0.f;

    auto issue = [&](int c, uint32_t stg) {
        const size_t k0 = (size_t)c * 64;
        #pragma unroll
        for (int i = 0; i < 16; ++i) {
            int arr = i >> 1;
            int idx = ((i & 1) << 8) + t;
            int row = idx >> 3, kg = (idx & 7) * 8;
            CP16(stg + arr * D_ARR + (uint32_t)row * 144 + kg * 2,
                 srcs[arr] + (size_t)row * LH + k0 + kg);
        }
        CP_COMMIT();
    };

    issue(0, sb);
    for (int c = 0; c < 32; ++c) {
        if (c < 31) { issue(c + 1, sb + ((c + 1) & 1) * D_STG); CP_WAIT1(); }
        else        { CP_WAIT0(); }
        __syncthreads();
        const uint32_t stg = sb + (c & 1) * D_STG;
        const uint32_t aHi = stg + grp * (2 * D_ARR) + aoff;
        const uint32_t aLo = aHi + D_ARR;
        const uint32_t bHi = stg + 4 * D_ARR + grp * (2 * D_ARR) + boff;
        const uint32_t bLo = bHi + D_ARR;
        #pragma unroll
        for (int ks = 0; ks < 4; ++ks) {
            uint32_t ah[4], al[4];
            ldsm4(ah, aHi + ks * 32);
            ldsm4(al, aLo + ks * 32);
            #pragma unroll
            for (int j = 0; j < 4; ++j) {
                uint32_t bh_[4], bl_[4];
                ldsm4(bh_, bHi + j * 2304 + ks * 32);
                ldsm4(bl_, bLo + j * 2304 + ks * 32);
                mma16816(acc[2 * j],     ah, bh_);
                mma16816(acc[2 * j],     ah, bl_);
                mma16816(acc[2 * j],     al, bh_);
                mma16816(acc[2 * j + 1], ah, bh_ + 2);
                mma16816(acc[2 * j + 1], ah, bl_ + 2);
                mma16816(acc[2 * j + 1], al, bh_ + 2);
            }
        }
        __syncthreads();
    }

    // epilogue: local row r -> f2 = 2r - (r&1) + 2*grp;  X[bh][e][f2]
    const int g = lane >> 2, q4 = lane & 3;
    float* xb = g_X + (size_t)bh * 8192;
    const int r0 = wr * 16 + g, r1 = r0 + 8;
    const int f2a = 2 * r0 - (r0 & 1) + 2 * grp;
    const int f2b = 2 * r1 - (r1 & 1) + 2 * grp;
    #pragma unroll
    for (int j = 0; j < 8; ++j) {
        int e0 = j * 8 + q4 * 2;
        xb[e0 * 128 + f2a]       = acc[j][0];
        xb[(e0 + 1) * 128 + f2a] = acc[j][1];
        xb[e0 * 128 + f2b]       = acc[j][2];
        xb[(e0 + 1) * 128 + f2b] = acc[j][3];
    }
}

// ---------------------------------------------------------------- Stage 2: mix
// Block = (h, og: 8 o, bq: 4 b). Emits parity-split C.
#define MIX_SMEM 98304       // Ws_r 32K | Ws_i 32K | Xs 32K
__global__ __launch_bounds__(256) void mix_kernel(const float* __restrict__ wr,
                                                  const float* __restrict__ wi) {
    extern __shared__ char sm[];
    float* Ws_r = (float*)sm;                // [16e][8o][64m]
    float* Ws_i = (float*)(sm + 32768);
    float* Xs   = (float*)(sm + 65536);      // [4b][16e][128]
    const int h = blockIdx.x & 7, og = (blockIdx.x >> 3) & 7, bq = blockIdx.x >> 6;
    const int t = threadIdx.x;
    const int f2 = t & 31, ol = t >> 5;

    float acc[4][4];
    #pragma unroll
    for (int i = 0; i < 4; ++i)
        #pragma unroll
        for (int j = 0; j < 4; ++j) acc[i][j] = 0.f;

    for (int e0 = 0; e0 < 64; e0 += 16) {
        __syncthreads();
        #pragma unroll
        for (int i = 0; i < 8; ++i) {        // W chunk
            int c = t + i * 256;
            int row = c >> 4, m4 = (c & 15) * 4;
            int e = row >> 3, o = row & 7;
            size_t g = (((size_t)h * 64 + e0 + e) * 64 + og * 8 + o) * 64 + m4;
            *(float4*)&Ws_r[(e * 8 + o) * 64 + m4] = *(const float4*)&wr[g];
            *(float4*)&Ws_i[(e * 8 + o) * 64 + m4] = *(const float4*)&wi[g];
        }
        #pragma unroll
        for (int i = 0; i < 8; ++i) {        // X chunk
            int c = t + i * 256;
            int row = c >> 5, f4 = (c & 31) * 4;
            int b = row >> 4, e = row & 15;
            int bh = (bq * 4 + b) * 8 + h;
            *(float4*)&Xs[(b * 16 + e) * 128 + f4] =
                *(const float4*)&g_X[(size_t)bh * 8192 + (e0 + e) * 128 + f4];
        }
        __syncthreads();
        #pragma unroll 4
        for (int e = 0; e < 16; ++e) {
            float2 w_r = *(float2*)&Ws_r[(e * 8 + ol) * 64 + 2 * f2];
            float2 w_i = *(float2*)&Ws_i[(e * 8 + ol) * 64 + 2 * f2];
            #pragma unroll
            for (int b = 0; b < 4; ++b) {
                float4 x = *(float4*)&Xs[(b * 16 + e) * 128 + 4 * f2];
                acc[b][0] += x.x * w_r.x - x.y * w_i.x;
                acc[b][1] += x.x * w_i.x + x.y * w_r.x;
                acc[b][2] += x.z * w_r.y - x.w * w_i.y;
                acc[b][3] += x.z * w_i.y + x.w * w_r.y;
            }
        }
    }
    const float a0 = (f2 == 0) ? (1.0f / 4096.0f) : (2.0f / 4096.0f);
    const float a1 = 2.0f / 4096.0f;
    #pragma unroll
    for (int b = 0; b < 4; ++b) {
        size_t row = (size_t)((bq * 4 + b) * 8 + h) * 64 + og * 8 + ol;
        // even freq f=2*f2 -> Ce cols {2*f2, 2*f2+1}; odd f=2*f2+1 -> Co
        float ve0 = a0 * acc[b][0], ve1 = -a0 * acc[b][1];
        float vo0 = a1 * acc[b][2], vo1 = -a1 * acc[b][3];
        union { uint32_t u; __nv_bfloat16 x[2]; } p;
        __nv_bfloat16 hi, lo, hi2, lo2;
        split_bf16(ve0, hi, lo);  split_bf16(ve1, hi2, lo2);
        p.x[0] = hi;  p.x[1] = hi2;  *(uint32_t*)&g_Ce_hi[row * 64 + 2 * f2] = p.u;
        p.x[0] = lo;  p.x[1] = lo2;  *(uint32_t*)&g_Ce_lo[row * 64 + 2 * f2] = p.u;
        split_bf16(vo0, hi, lo);  split_bf16(vo1, hi2, lo2);
        p.x[0] = hi;  p.x[1] = hi2;  *(uint32_t*)&g_Co_hi[row * 64 + 2 * f2] = p.u;
        p.x[0] = lo;  p.x[1] = lo2;  *(uint32_t*)&g_Co_lo[row * 64 + 2 * f2] = p.u;
    }
}

// ---------------------------------------------------------------- Stage 3: iDFT
// CTA = (bh-pair p, 128-l chunk lc of half-domain). E = Ce*Gte^T, O = Co*Gto^T
// (each K=64); out(l)=E+O, out(l+2048)=E-O.
#define I_ARR  18432                 // 128 rows * 144B
#define IDFT_SMEM (8 * I_ARR)        // 147456

__global__ __launch_bounds__(256) void idft_mma_kernel(float* __restrict__ out) {
    extern __shared__ char smi[];
    const uint32_t sb = smem_u32(smi);
    const int p = blockIdx.x & 63, lc = blockIdx.x >> 6;   // lc 0..15
    const int t = threadIdx.x;
    const int w = t >> 5, lane = t & 31;
    const size_t pC = (size_t)p * 128 * 64;
    const size_t lG = (size_t)lc * 128 * 64;

    const __nv_bfloat16* srcs[8] = {
        g_Ce_hi + pC, g_Ce_lo + pC, g_Co_hi + pC, g_Co_lo + pC,
        g_Gte_hi + lG, g_Gte_lo + lG, g_Gto_hi + lG, g_Gto_lo + lG };

    #pragma unroll
    for (int i = 0; i < 32; ++i) {
        int arr = i >> 2;
        int idx = ((i & 3) << 8) + t;
        int row = idx >> 3, kg = (idx & 7) * 8;
        CP16(sb + arr * I_ARR + (uint32_t)row * 144 + kg * 2,
             srcs[arr] + (size_t)row * 64 + kg);
    }
    CP_COMMIT();
    CP_WAIT0();
    __syncthreads();

    const uint32_t aoff = (uint32_t)(w * 16 + (lane & 15)) * 144 + (lane >> 4) * 16;
    const uint32_t boff = (uint32_t)((lane >> 4) * 8 + (lane & 7)) * 144 + ((lane >> 3) & 1) * 16;

    float accE[16][4], accO[16][4];
    #pragma unroll
    for (int i = 0; i < 16; ++i)
        #pragma unroll
        for (int j = 0; j < 4; ++j) { accE[i][j] = 0.f; accO[i][j] = 0.f; }

    #pragma unroll
    for (int grp = 0; grp < 2; ++grp) {
        float (*acc)[4] = grp ? accO : accE;
        const uint32_t aHi = sb + grp * (2 * I_ARR) + aoff;
        const uint32_t aLo = aHi + I_ARR;
        const uint32_t bHi = sb + 4 * I_ARR + grp * (2 * I_ARR) + boff;
        const uint32_t bLo = bHi + I_ARR;
        #pragma unroll
        for (int ks = 0; ks < 4; ++ks) {
            uint32_t ah[4], al[4];
            ldsm4(ah, aHi + ks * 32);
            ldsm4(al, aLo + ks * 32);
            #pragma unroll
            for (int j = 0; j < 8; ++j) {
                uint32_t bh_[4], bl_[4];
                ldsm4(bh_, bHi + j * 2304 + ks * 32);
                ldsm4(bl_, bLo + j * 2304 + ks * 32);
                mma16816(acc[2 * j],     ah, bh_);
                mma16816(acc[2 * j],     ah, bl_);
                mma16816(acc[2 * j],     al, bh_);
                mma16816(acc[2 * j + 1], ah, bh_ + 2);
                mma16816(acc[2 * j + 1], ah, bl_ + 2);
                mma16816(acc[2 * j + 1], al, bh_ + 2);
            }
        }
    }

    // epilogue: rows p*128 + w*16 + {g, g+8}; half-l cols lc*128 + j*8 + q4*2
    const int g = lane >> 2, q4 = lane & 3;
    float* o0 = out + ((size_t)p * 128 + w * 16 + g) * LSEQ + lc * 128 + q4 * 2;
    float* o1 = o0 + (size_t)8 * LSEQ;
    #pragma unroll
    for (int j = 0; j < 16; ++j) {
        *(float2*)(o0 + j * 8) =
            make_float2(accE[j][0] + accO[j][0], accE[j][1] + accO[j][1]);
        *(float2*)(o0 + LH + j * 8) =
            make_float2(accE[j][0] - accO[j][0], accE[j][1] - accO[j][1]);
        *(float2*)(o1 + j * 8) =
            make_float2(accE[j][2] + accO[j][2], accE[j][3] + accO[j][3]);
        *(float2*)(o1 + LH + j * 8) =
            make_float2(accE[j][2] - accO[j][2], accE[j][3] - accO[j][3]);
    }
}

// ---------------------------------------------------------------------------
extern "C" void kernel_launch(void* const* d_in, const int* in_sizes, int n_in,
                              void* d_out, int out_size) {
    const float* q = (const float*)d_in[0];
    const float* wr = nullptr;
    const float* wi = nullptr;
    for (int i = 0; i < n_in; ++i) {
        if (in_sizes[i] == 8 * 64 * 64 * 64) {
            if (!wr) wr = (const float*)d_in[i];
            else if (!wi) wi = (const float*)d_in[i];
        }
    }
    float* out = (float*)d_out;

    cudaFuncSetAttribute(dft_mma_kernel,  cudaFuncAttributeMaxDynamicSharedMemorySize, DFT_SMEM);
    cudaFuncSetAttribute(mix_kernel,      cudaFuncAttributeMaxDynamicSharedMemorySize, MIX_SMEM);
    cudaFuncSetAttribute(idft_mma_kernel, cudaFuncAttributeMaxDynamicSharedMemorySize, IDFT_SMEM);

    init_basis_kernel<<<512, 256>>>();
    transpose_bfly_kernel<<<NBH * 32, 256>>>(q);
    dft_mma_kernel<<<NBH, 256, DFT_SMEM>>>();
    mix_kernel<<<256, 256, MIX_SMEM>>>(wr, wi);
    idft_mma_kernel<<<64 * 16, 256, IDFT_SMEM>>>(out);
}

// round 8
// speedup vs baseline: 3.1872x; 1.2752x over previous
#include <cuda_runtime.h>
#include <cuda_bf16.h>
#include <cstdint>
#include <cstddef>

#define LSEQ 4096
#define LH   2048
#define NBH  128

// ------------------------------------------------------------- gmem scratch
__device__ __nv_bfloat16 g_Fu_hi[64 * LH], g_Fu_lo[64 * LH];   // fwd basis even-f rows
__device__ __nv_bfloat16 g_Fv_hi[64 * LH], g_Fv_lo[64 * LH];   // fwd basis odd-f rows
__device__ __nv_bfloat16 g_Gte_hi[LH * 64], g_Gte_lo[LH * 64]; // inv basis even parity
__device__ __nv_bfloat16 g_Gto_hi[LH * 64], g_Gto_lo[LH * 64]; // inv basis odd parity
__device__ float         g_X[NBH * 64 * 128];                  // [bh][e][f2]
__device__ __nv_bfloat16 g_Ce_hi[NBH * 64 * 64], g_Ce_lo[NBH * 64 * 64];
__device__ __nv_bfloat16 g_Co_hi[NBH * 64 * 64], g_Co_lo[NBH * 64 * 64];

// ------------------------------------------------------------- helpers
__device__ __forceinline__ uint32_t smem_u32(const void* p) {
    uint32_t a;
    asm("{ .reg .u64 t; cvta.to.shared.u64 t, %1; cvt.u32.u64 %0, t; }" : "=r"(a) : "l"(p));
    return a;
}
__device__ __forceinline__ void split_bf16(float x, __nv_bfloat16& hi, __nv_bfloat16& lo) {
    hi = __float2bfloat16(x);
    lo = __float2bfloat16(x - __bfloat162float(hi));
}
__device__ __forceinline__ void ldsm4(uint32_t* r, uint32_t addr) {
    asm volatile("ldmatrix.sync.aligned.m8n8.x4.shared.b16 {%0,%1,%2,%3}, [%4];"
                 : "=r"(r[0]), "=r"(r[1]), "=r"(r[2]), "=r"(r[3]) : "r"(addr));
}
__device__ __forceinline__ void ldsm4t(uint32_t* r, uint32_t addr) {
    asm volatile("ldmatrix.sync.aligned.m8n8.x4.trans.shared.b16 {%0,%1,%2,%3}, [%4];"
                 : "=r"(r[0]), "=r"(r[1]), "=r"(r[2]), "=r"(r[3]) : "r"(addr));
}
__device__ __forceinline__ void mma16816(float* d, const uint32_t* a, const uint32_t* b) {
    asm volatile("mma.sync.aligned.m16n8k16.row.col.f32.bf16.bf16.f32 "
                 "{%0,%1,%2,%3}, {%4,%5,%6,%7}, {%8,%9}, {%0,%1,%2,%3};"
                 : "+f"(d[0]), "+f"(d[1]), "+f"(d[2]), "+f"(d[3])
                 : "r"(a[0]), "r"(a[1]), "r"(a[2]), "r"(a[3]), "r"(b[0]), "r"(b[1]));
}
#define CP16(sa, gp) asm volatile("cp.async.cg.shared.global [%0], [%1], 16;" \
                                  :: "r"((uint32_t)(sa)), "l"(gp) : "memory")
#define CP_COMMIT()  asm volatile("cp.async.commit_group;" ::: "memory")
#define CP_WAIT0()   asm volatile("cp.async.wait_group 0;" ::: "memory")
#define CP_WAIT1()   asm volatile("cp.async.wait_group 1;" ::: "memory")

// ---------------------------------------------------------------- basis init
__global__ void init_basis_kernel() {
    int idx = blockIdx.x * 256 + threadIdx.x;      // < 131072
    {   // Fu/Fv rows ru = 2*fe + c (c=0 cos, c=1 -sin), half domain
        int ru = idx >> 11, l = idx & 2047;
        int fe = ru >> 1, c = ru & 1;
        float s, cs;
        __nv_bfloat16 hi, lo;
        sincospif((float)((l * (2 * fe)) & 4095) / 2048.0f, &s, &cs);
        split_bf16(c ? -s : cs, hi, lo);
        g_Fu_hi[ru * LH + l] = hi;  g_Fu_lo[ru * LH + l] = lo;
        sincospif((float)((l * (2 * fe + 1)) & 4095) / 2048.0f, &s, &cs);
        split_bf16(c ? -s : cs, hi, lo);
        g_Fv_hi[ru * LH + l] = hi;  g_Fv_lo[ru * LH + l] = lo;
    }
    {   // Gte/Gto: [l][kk=2*fe+c], c=0 cos, c=1 +sin
        int l = idx >> 6, kk = idx & 63;
        int fe = kk >> 1, c = kk & 1;
        float s, cs;
        __nv_bfloat16 hi, lo;
        sincospif((float)((l * (2 * fe)) & 4095) / 2048.0f, &s, &cs);
        split_bf16(c ? s : cs, hi, lo);
        g_Gte_hi[l * 64 + kk] = hi;  g_Gte_lo[l * 64 + kk] = lo;
        sincospif((float)((l * (2 * fe + 1)) & 4095) / 2048.0f, &s, &cs);
        split_bf16(c ? s : cs, hi, lo);
        g_Gto_hi[l * 64 + kk] = hi;  g_Gto_lo[l * 64 + kk] = lo;
    }
}

// ---------------------------------------------------------------- Stage 1: DFT
// Fused: q LDG -> butterfly -> hi/lo split -> smem [l][e] tiles -> HMMA (trans B).
// CTA/bh, 32 chunks of 64 half-l. F basis cp.async double-buffered; q reg-prefetched.
#define D_ARR  9216                  // 64 rows * 144B
#define F_STG  (4 * D_ARR)           // Fu_hi|Fu_lo|Fv_hi|Fv_lo
#define DFT_SMEM (4 * F_STG)         // Fstg0|Fstg1|UVbuf0|UVbuf1 = 147456

__global__ __launch_bounds__(256) void dft_fused_kernel(const float* __restrict__ q) {
    extern __shared__ char smd[];
    const uint32_t sb = smem_u32(smd);
    const int bh = blockIdx.x, b = bh >> 3, h = bh & 7;
    const int t = threadIdx.x, w = t >> 5, lane = t & 31;
    const int grp = w >> 2, wr = w & 3;
    const float* qb = q + ((size_t)b * LSEQ * 8 + h) * 64;   // q[b][l][h][e]

    const __nv_bfloat16* srcF[4] = { g_Fu_hi, g_Fu_lo, g_Fv_hi, g_Fv_lo };

    // q LDG: thread covers rows l = (t>>4) + 16*pass, 4 floats at (t&15)*4
    const int ql = t >> 4, qe4 = (t & 15) * 4;
    float4 ra[4], rb[4];
    auto LDGQ = [&](int l0) {
        #pragma unroll
        for (int ps = 0; ps < 4; ++ps) {
            const float* p = qb + (size_t)(l0 + ql + ps * 16) * 512 + qe4;
            ra[ps] = *(const float4*)p;
            rb[ps] = *(const float4*)(p + (size_t)LH * 512);
        }
    };
    auto issueF = [&](int c, uint32_t stg) {
        const size_t k0 = (size_t)c * 64;
        #pragma unroll
        for (int i = 0; i < 8; ++i) {
            int arr = i >> 1;
            int idx = ((i & 1) << 8) + t;
            int row = idx >> 3, kg = (idx & 7) * 8;
            CP16(stg + arr * D_ARR + (uint32_t)row * 144 + kg * 2,
                 srcF[arr] + (size_t)row * LH + k0 + kg);
        }
        CP_COMMIT();
    };
    auto convert = [&](uint32_t uvb) {      // uv tiles [l][e], rows 144B
        #pragma unroll
        for (int ps = 0; ps < 4; ++ps) {
            int l = ql + ps * 16;
            uint32_t ad = uvb + (uint32_t)l * 144 + (t & 15) * 8;
            float4 a = ra[ps], bb = rb[ps];
            float uv[2][4] = {{a.x + bb.x, a.y + bb.y, a.z + bb.z, a.w + bb.w},
                              {a.x - bb.x, a.y - bb.y, a.z - bb.z, a.w - bb.w}};
            #pragma unroll
            for (int s = 0; s < 2; ++s) {
                union { uint32_t u[2]; __nv_bfloat16 x[4]; } H, L;
                #pragma unroll
                for (int j = 0; j < 4; ++j) {
                    __nv_bfloat16 hi, lo;
                    split_bf16(uv[s][j], hi, lo);
                    H.x[j] = hi;  L.x[j] = lo;
                }
                *(uint2*)(smd + (ad - sb) + s * 2 * D_ARR)        = make_uint2(H.u[0], H.u[1]);
                *(uint2*)(smd + (ad - sb) + s * 2 * D_ARR + D_ARR) = make_uint2(L.u[0], L.u[1]);
            }
        }
    };

    const uint32_t aoff = (uint32_t)(wr * 16 + (lane & 15)) * 144 + (lane >> 4) * 16;
    const uint32_t boff = (uint32_t)(lane & 15) * 144 + (lane >> 4) * 16;   // trans: rows=k(l)

    float acc[8][4];
    #pragma unroll
    for (int i = 0; i < 8; ++i)
        #pragma unroll
        for (int j = 0; j < 4; ++j) acc[i][j] = 0.f;

    LDGQ(0);
    issueF(0, sb);
    for (int c = 0; c < 32; ++c) {
        const uint32_t uvb = sb + 2 * F_STG + (uint32_t)(c & 1) * F_STG;
        convert(uvb);
        if (c < 31) {
            LDGQ((c + 1) * 64);
            issueF(c + 1, sb + (uint32_t)((c + 1) & 1) * F_STG);
            CP_WAIT1();
        } else CP_WAIT0();
        __syncthreads();
        const uint32_t fst = sb + (uint32_t)(c & 1) * F_STG;
        const uint32_t aHi = fst + grp * (2 * D_ARR) + aoff, aLo = aHi + D_ARR;
        const uint32_t bHi = uvb + grp * (2 * D_ARR) + boff, bLo = bHi + D_ARR;
        #pragma unroll
        for (int ks = 0; ks < 4; ++ks) {
            uint32_t ah[4], al[4];
            ldsm4(ah, aHi + ks * 32);               // A: rows f, cols l(K)
            ldsm4(al, aLo + ks * 32);
            #pragma unroll
            for (int j = 0; j < 4; ++j) {
                uint32_t bh_[4], bl_[4];
                ldsm4t(bh_, bHi + ks * 2304 + j * 32);   // B: rows l(K), cols e(N)
                ldsm4t(bl_, bLo + ks * 2304 + j * 32);
                mma16816(acc[2 * j],     ah, bh_);
                mma16816(acc[2 * j],     ah, bl_);
                mma16816(acc[2 * j],     al, bh_);
                mma16816(acc[2 * j + 1], ah, bh_ + 2);
                mma16816(acc[2 * j + 1], ah, bl_ + 2);
                mma16816(acc[2 * j + 1], al, bh_ + 2);
            }
        }
        __syncthreads();
    }

    // epilogue: local row r -> f2 = 2r - (r&1) + 2*grp;  X[bh][e][f2]
    const int g = lane >> 2, q4 = lane & 3;
    float* xb = g_X + (size_t)bh * 8192;
    const int r0 = wr * 16 + g, r1 = r0 + 8;
    const int f2a = 2 * r0 - (r0 & 1) + 2 * grp;
    const int f2b = 2 * r1 - (r1 & 1) + 2 * grp;
    #pragma unroll
    for (int j = 0; j < 8; ++j) {
        int e0 = j * 8 + q4 * 2;
        xb[e0 * 128 + f2a]       = acc[j][0];
        xb[(e0 + 1) * 128 + f2a] = acc[j][1];
        xb[e0 * 128 + f2b]       = acc[j][2];
        xb[(e0 + 1) * 128 + f2b] = acc[j][3];
    }
}

// ---------------------------------------------------------------- Stage 2: mix
#define MIX_SMEM 98304       // Ws_r 32K | Ws_i 32K | Xs 32K
__global__ __launch_bounds__(256) void mix_kernel(const float* __restrict__ wr,
                                                  const float* __restrict__ wi) {
    extern __shared__ char sm[];
    float* Ws_r = (float*)sm;
    float* Ws_i = (float*)(sm + 32768);
    float* Xs   = (float*)(sm + 65536);
    const int h = blockIdx.x & 7, og = (blockIdx.x >> 3) & 7, bq = blockIdx.x >> 6;
    const int t = threadIdx.x;
    const int f2 = t & 31, ol = t >> 5;

    float acc[4][4];
    #pragma unroll
    for (int i = 0; i < 4; ++i)
        #pragma unroll
        for (int j = 0; j < 4; ++j) acc[i][j] = 0.f;

    for (int e0 = 0; e0 < 64; e0 += 16) {
        __syncthreads();
        #pragma unroll
        for (int i = 0; i < 8; ++i) {
            int c = t + i * 256;
            int row = c >> 4, m4 = (c & 15) * 4;
            int e = row >> 3, o = row & 7;
            size_t g = (((size_t)h * 64 + e0 + e) * 64 + og * 8 + o) * 64 + m4;
            *(float4*)&Ws_r[(e * 8 + o) * 64 + m4] = *(const float4*)&wr[g];
            *(float4*)&Ws_i[(e * 8 + o) * 64 + m4] = *(const float4*)&wi[g];
        }
        #pragma unroll
        for (int i = 0; i < 8; ++i) {
            int c = t + i * 256;
            int row = c >> 5, f4 = (c & 31) * 4;
            int b = row >> 4, e = row & 15;
            int bh = (bq * 4 + b) * 8 + h;
            *(float4*)&Xs[(b * 16 + e) * 128 + f4] =
                *(const float4*)&g_X[(size_t)bh * 8192 + (e0 + e) * 128 + f4];
        }
        __syncthreads();
        #pragma unroll 4
        for (int e = 0; e < 16; ++e) {
            float2 w_r = *(float2*)&Ws_r[(e * 8 + ol) * 64 + 2 * f2];
            float2 w_i = *(float2*)&Ws_i[(e * 8 + ol) * 64 + 2 * f2];
            #pragma unroll
            for (int b = 0; b < 4; ++b) {
                float4 x = *(float4*)&Xs[(b * 16 + e) * 128 + 4 * f2];
                acc[b][0] += x.x * w_r.x - x.y * w_i.x;
                acc[b][1] += x.x * w_i.x + x.y * w_r.x;
                acc[b][2] += x.z * w_r.y - x.w * w_i.y;
                acc[b][3] += x.z * w_i.y + x.w * w_r.y;
            }
        }
    }
    const float a0 = (f2 == 0) ? (1.0f / 4096.0f) : (2.0f / 4096.0f);
    const float a1 = 2.0f / 4096.0f;
    #pragma unroll
    for (int b = 0; b < 4; ++b) {
        size_t row = (size_t)((bq * 4 + b) * 8 + h) * 64 + og * 8 + ol;
        float ve0 = a0 * acc[b][0], ve1 = -a0 * acc[b][1];
        float vo0 = a1 * acc[b][2], vo1 = -a1 * acc[b][3];
        union { uint32_t u; __nv_bfloat16 x[2]; } p;
        __nv_bfloat16 hi, lo, hi2, lo2;
        split_bf16(ve0, hi, lo);  split_bf16(ve1, hi2, lo2);
        p.x[0] = hi;  p.x[1] = hi2;  *(uint32_t*)&g_Ce_hi[row * 64 + 2 * f2] = p.u;
        p.x[0] = lo;  p.x[1] = lo2;  *(uint32_t*)&g_Ce_lo[row * 64 + 2 * f2] = p.u;
        split_bf16(vo0, hi, lo);  split_bf16(vo1, hi2, lo2);
        p.x[0] = hi;  p.x[1] = hi2;  *(uint32_t*)&g_Co_hi[row * 64 + 2 * f2] = p.u;
        p.x[0] = lo;  p.x[1] = lo2;  *(uint32_t*)&g_Co_lo[row * 64 + 2 * f2] = p.u;
    }
}

// ---------------------------------------------------------------- Stage 3: iDFT
// CTA = (p: bh-pair, lq: quarter). 4 l-chunks of 128 per CTA; A loaded once,
// G double-buffered. out(l)=E+O, out(l+2048)=E-O.
#define I_ARR  18432                 // 128 rows * 144B
#define I_A    (4 * I_ARR)           // Ce_hi|Ce_lo|Co_hi|Co_lo = 73728
#define I_G    (4 * I_ARR)           // Gte_hi|Gte_lo|Gto_hi|Gto_lo per stage
#define IDFT_SMEM (I_A + 2 * I_G)    // 221184

__global__ __launch_bounds__(256) void idft_mma_kernel(float* __restrict__ out) {
    extern __shared__ char smi[];
    const uint32_t sb = smem_u32(smi);
    const int p = blockIdx.x & 63, lq = blockIdx.x >> 6;   // lq 0..3
    const int t = threadIdx.x, w = t >> 5, lane = t & 31;
    const size_t pC = (size_t)p * 128 * 64;

    const __nv_bfloat16* srcA[4] = { g_Ce_hi + pC, g_Ce_lo + pC, g_Co_hi + pC, g_Co_lo + pC };
    const __nv_bfloat16* srcG[4] = { g_Gte_hi, g_Gte_lo, g_Gto_hi, g_Gto_lo };

    auto issueG = [&](int lc, uint32_t stg) {
        const size_t lG = (size_t)lc * 128 * 64;
        #pragma unroll
        for (int i = 0; i < 16; ++i) {
            int arr = i >> 2;
            int idx = ((i & 3) << 8) + t;
            int row = idx >> 3, kg = (idx & 7) * 8;
            CP16(stg + arr * I_ARR + (uint32_t)row * 144 + kg * 2,
                 srcG[arr] + lG + (size_t)row * 64 + kg);
        }
        CP_COMMIT();
    };

    // A once + G[lq*4]
    #pragma unroll
    for (int i = 0; i < 16; ++i) {
        int arr = i >> 2;
        int idx = ((i & 3) << 8) + t;
        int row = idx >> 3, kg = (idx & 7) * 8;
        CP16(sb + arr * I_ARR + (uint32_t)row * 144 + kg * 2,
             srcA[arr] + (size_t)row * 64 + kg);
    }
    issueG(lq * 4, sb + I_A);        // A + G0 in one group

    const uint32_t aoff = (uint32_t)(w * 16 + (lane & 15)) * 144 + (lane >> 4) * 16;
    const uint32_t boff = (uint32_t)((lane >> 4) * 8 + (lane & 7)) * 144 + ((lane >> 3) & 1) * 16;
    const int g = lane >> 2, q4 = lane & 3;

    for (int cc = 0; cc < 4; ++cc) {
        const int lc = lq * 4 + cc;
        if (cc < 3) { issueG(lc + 1, sb + I_A + (uint32_t)((cc + 1) & 1) * I_G); CP_WAIT1(); }
        else        { CP_WAIT0(); }
        __syncthreads();

        float accE[16][4], accO[16][4];
        #pragma unroll
        for (int i = 0; i < 16; ++i)
            #pragma unroll
            for (int j = 0; j < 4; ++j) { accE[i][j] = 0.f; accO[i][j] = 0.f; }

        const uint32_t gst = sb + I_A + (uint32_t)(cc & 1) * I_G;
        #pragma unroll
        for (int grp = 0; grp < 2; ++grp) {
            float (*acc)[4] = grp ? accO : accE;
            const uint32_t aHi = sb + grp * (2 * I_ARR) + aoff, aLo = aHi + I_ARR;
            const uint32_t bHi = gst + grp * (2 * I_ARR) + boff, bLo = bHi + I_ARR;
            #pragma unroll
            for (int ks = 0; ks < 4; ++ks) {
                uint32_t ah[4], al[4];
                ldsm4(ah, aHi + ks * 32);
                ldsm4(al, aLo + ks * 32);
                #pragma unroll
                for (int j = 0; j < 8; ++j) {
                    uint32_t bh_[4], bl_[4];
                    ldsm4(bh_, bHi + j * 2304 + ks * 32);
                    ldsm4(bl_, bLo + j * 2304 + ks * 32);
                    mma16816(acc[2 * j],     ah, bh_);
                    mma16816(acc[2 * j],     ah, bl_);
                    mma16816(acc[2 * j],     al, bh_);
                    mma16816(acc[2 * j + 1], ah, bh_ + 2);
                    mma16816(acc[2 * j + 1], ah, bl_ + 2);
                    mma16816(acc[2 * j + 1], al, bh_ + 2);
                }
            }
        }

        float* o0 = out + ((size_t)p * 128 + w * 16 + g) * LSEQ + lc * 128 + q4 * 2;
        float* o1 = o0 + (size_t)8 * LSEQ;
        #pragma unroll
        for (int j = 0; j < 16; ++j) {
            *(float2*)(o0 + j * 8) =
                make_float2(accE[j][0] + accO[j][0], accE[j][1] + accO[j][1]);
            *(float2*)(o0 + LH + j * 8) =
                make_float2(accE[j][0] - accO[j][0], accE[j][1] - accO[j][1]);
            *(float2*)(o1 + j * 8) =
                make_float2(accE[j][2] + accO[j][2], accE[j][3] + accO[j][3]);
            *(float2*)(o1 + LH + j * 8) =
                make_float2(accE[j][2] - accO[j][2], accE[j][3] - accO[j][3]);
        }
        __syncthreads();
    }
}

// ---------------------------------------------------------------------------
extern "C" void kernel_launch(void* const* d_in, const int* in_sizes, int n_in,
                              void* d_out, int out_size) {
    const float* q = (const float*)d_in[0];
    const float* wr = nullptr;
    const float* wi = nullptr;
    for (int i = 0; i < n_in; ++i) {
        if (in_sizes[i] == 8 * 64 * 64 * 64) {
            if (!wr) wr = (const float*)d_in[i];
            else if (!wi) wi = (const float*)d_in[i];
        }
    }
    float* out = (float*)d_out;

    cudaFuncSetAttribute(dft_fused_kernel, cudaFuncAttributeMaxDynamicSharedMemorySize, DFT_SMEM);
    cudaFuncSetAttribute(mix_kernel,       cudaFuncAttributeMaxDynamicSharedMemorySize, MIX_SMEM);
    cudaFuncSetAttribute(idft_mma_kernel,  cudaFuncAttributeMaxDynamicSharedMemorySize, IDFT_SMEM);

    init_basis_kernel<<<512, 256>>>();
    dft_fused_kernel<<<NBH, 256, DFT_SMEM>>>(q);
    mix_kernel<<<256, 256, MIX_SMEM>>>(wr, wi);
    idft_mma_kernel<<<256, 256, IDFT_SMEM>>>(out);
}